// round 14
// baseline (speedup 1.0000x reference)
#include <cuda_runtime.h>
#include <cuda_bf16.h>
#include <cstdint>

// AttentionPooling: B=64, S=4096, D=256, fp32.
//   LN(x) over D -> Dense(1) score -> softmax over S -> out[b,d] = sum_s x_s * w_s
// One pass over x via TMA bulk pipeline: each CTA's 128KB chunk is contiguous,
// streamed as 32KB stages by cp.async.bulk (single-thread issue, mbarrier
// complete_tx) into a 3-deep smem ring. Consumers (8 warps, 4 rows/warp/stage)
// read via conflict-free LDS and run the online-softmax body. DRAM is fed by
// the TMA engine, decoupled from warp scheduling. Fused last-block combine.

#define BDIM   64
#define SDIM   4096
#define DDIM   256
#define CHUNKS 32
#define RPC    (SDIM / CHUNKS)       /* 128 rows per block */
#define WARPS  8
#define NTHR   (WARPS * 32)
#define STAGE_ROWS 32
#define STAGE_BYTES (STAGE_ROWS * DDIM * 4)   /* 32 KB */
#define DEPTH  3
#define NSTG   (RPC / STAGE_ROWS)    /* 4 stages per CTA */
#define RB     4                     /* rows per warp per stage */
#define LN_EPS 1e-3f

// Split-softmax partial scratch + completion counters (static device globals).
__device__ float g_pacc[BDIM * CHUNKS * DDIM];   // 2 MB
__device__ float g_pm[BDIM * CHUNKS];
__device__ float g_pl[BDIM * CHUNKS];
__device__ int   g_cnt[BDIM];                    // zero-init; self-resetting

__device__ __forceinline__ float warp_sum(float v) {
    #pragma unroll
    for (int o = 16; o > 0; o >>= 1) v += __shfl_xor_sync(0xffffffffu, v, o);
    return v;
}

__device__ __forceinline__ uint32_t smem_u32(const void* p) {
    return (uint32_t)__cvta_generic_to_shared(p);
}

__device__ __forceinline__ void mbar_init(uint32_t mbar, uint32_t count) {
    asm volatile("mbarrier.init.shared.b64 [%0], %1;" :: "r"(mbar), "r"(count) : "memory");
}
__device__ __forceinline__ void mbar_expect_tx(uint32_t mbar, uint32_t bytes) {
    asm volatile("mbarrier.arrive.expect_tx.shared.b64 _, [%0], %1;"
                 :: "r"(mbar), "r"(bytes) : "memory");
}
__device__ __forceinline__ void mbar_wait(uint32_t mbar, uint32_t parity) {
    uint32_t done;
    asm volatile(
        "{\n\t.reg .pred p;\n\t"
        "mbarrier.try_wait.parity.acquire.cta.shared::cta.b64 p, [%1], %2;\n\t"
        "selp.b32 %0, 1, 0, p;\n\t}"
        : "=r"(done) : "r"(mbar), "r"(parity) : "memory");
    if (!done) {
        asm volatile(
            "{\n\t.reg .pred P1;\n\t"
            "WL_%=:\n\t"
            "mbarrier.try_wait.parity.acquire.cta.shared::cta.b64 P1, [%0], %1, 0x989680;\n\t"
            "@P1 bra.uni WD_%=;\n\t"
            "bra.uni WL_%=;\n\t"
            "WD_%=:\n\t}"
            :: "r"(mbar), "r"(parity) : "memory");
    }
}
__device__ __forceinline__ void tma_bulk_1d(uint32_t smem_dst, const void* gsrc,
                                            uint32_t bytes, uint32_t mbar) {
    asm volatile(
        "cp.async.bulk.shared::cta.global.mbarrier::complete_tx::bytes "
        "[%0], [%1], %2, [%3];"
        :: "r"(smem_dst), "l"(gsrc), "r"(bytes), "r"(mbar) : "memory");
}

__global__ __launch_bounds__(NTHR, 2)
void ap_fused(const float* __restrict__ x, const float* __restrict__ mask,
              const float* __restrict__ gamma, const float* __restrict__ beta,
              const float* __restrict__ w, const float* __restrict__ bias,
              float* __restrict__ out)
{
    extern __shared__ float stage_sm[];            // DEPTH * 32KB ring
    __shared__ uint64_t full_bar[DEPTH];

    const int b     = blockIdx.y;
    const int chunk = blockIdx.x;
    const int tid   = threadIdx.x;
    const int wid   = tid >> 5;
    const int lid   = tid & 31;

    const float* xb = x + (size_t)b * SDIM * DDIM;
    const float* mb = mask + (size_t)b * SDIM;
    const float* xchunk = xb + (size_t)chunk * RPC * DDIM;  // contiguous 128KB

    // Init mbarriers, then start the TMA pipeline.
    if (tid == 0) {
        #pragma unroll
        for (int s = 0; s < DEPTH; s++) mbar_init(smem_u32(&full_bar[s]), 1);
    }
    __syncthreads();
    if (tid == 0) {
        #pragma unroll
        for (int s = 0; s < DEPTH; s++) {
            const uint32_t mbar = smem_u32(&full_bar[s]);
            mbar_expect_tx(mbar, STAGE_BYTES);
            tma_bulk_1d(smem_u32(stage_sm + s * (STAGE_BYTES / 4)),
                        xchunk + (size_t)s * STAGE_ROWS * DDIM,
                        STAGE_BYTES, mbar);
        }
    }

    // Per-lane parameter slices: d = lid*4..lid*4+3 and 128+lid*4..
    const float4 gm0 = __ldg(((const float4*)gamma) + lid);
    const float4 gm1 = __ldg(((const float4*)gamma) + 32 + lid);
    const float4 ww0 = __ldg(((const float4*)w) + lid);
    const float4 ww1 = __ldg(((const float4*)w) + 32 + lid);
    const float4 bt0 = __ldg(((const float4*)beta) + lid);
    const float4 bt1 = __ldg(((const float4*)beta) + 32 + lid);

    float gw0[4] = {gm0.x*ww0.x, gm0.y*ww0.y, gm0.z*ww0.z, gm0.w*ww0.w};
    float gw1[4] = {gm1.x*ww1.x, gm1.y*ww1.y, gm1.z*ww1.z, gm1.w*ww1.w};

    const float sgw = warp_sum(gw0[0]+gw0[1]+gw0[2]+gw0[3]
                             + gw1[0]+gw1[1]+gw1[2]+gw1[3]);
    const float bw  = warp_sum(bt0.x*ww0.x + bt0.y*ww0.y + bt0.z*ww0.z + bt0.w*ww0.w
                             + bt1.x*ww1.x + bt1.y*ww1.y + bt1.z*ww1.z + bt1.w*ww1.w);
    const float score_c = bw + __ldg(bias);

    // Fold mu*sgw into the dot weight: gw' = gamma*w - sgw/D.
    #pragma unroll
    for (int j = 0; j < 4; j++) gw0[j] -= sgw * (1.0f / DDIM);
    #pragma unroll
    for (int j = 0; j < 4; j++) gw1[j] -= sgw * (1.0f / DDIM);

    // Online softmax state (per warp; acc distributed across lanes).
    float m = -3.0e38f, l = 0.0f;
    float acc0[4] = {0.f, 0.f, 0.f, 0.f};
    float acc1[4] = {0.f, 0.f, 0.f, 0.f};

    #pragma unroll
    for (int st = 0; st < NSTG; st++) {
        const int slot = st % DEPTH;
        const uint32_t parity = (st / DEPTH) & 1u;
        mbar_wait(smem_u32(&full_bar[slot]), parity);

        const float* stg = stage_sm + slot * (STAGE_BYTES / 4);
        // This warp's 4 rows within the stage: rows wid*4 .. wid*4+3.
        float4 xv0[RB], xv1[RB];
        #pragma unroll
        for (int k = 0; k < RB; k++) {
            const float4* srow = (const float4*)(stg + (wid * RB + k) * DDIM);
            xv0[k] = srow[lid];
            xv1[k] = srow[32 + lid];
        }
        const float4 mv = __ldg((const float4*)(mb + chunk * RPC
                                                + st * STAGE_ROWS + wid * RB));

        // Per-row partials: sum(x), sum(x^2), dot(x, gw')
        float s1[RB], s2[RB], sd[RB];
        #pragma unroll
        for (int k = 0; k < RB; k++) {
            const float4 a = xv0[k], c = xv1[k];
            s1[k] = a.x + a.y + a.z + a.w + c.x + c.y + c.z + c.w;
            s2[k] = a.x*a.x + a.y*a.y + a.z*a.z + a.w*a.w
                  + c.x*c.x + c.y*c.y + c.z*c.z + c.w*c.w;
            sd[k] = a.x*gw0[0] + a.y*gw0[1] + a.z*gw0[2] + a.w*gw0[3]
                  + c.x*gw1[0] + c.y*gw1[1] + c.z*gw1[2] + c.w*gw1[3];
        }
        // 12 concurrent butterfly chains, 5 rounds.
        #pragma unroll
        for (int o = 16; o > 0; o >>= 1) {
            #pragma unroll
            for (int k = 0; k < RB; k++) {
                s1[k] += __shfl_xor_sync(0xffffffffu, s1[k], o);
                s2[k] += __shfl_xor_sync(0xffffffffu, s2[k], o);
                sd[k] += __shfl_xor_sync(0xffffffffu, sd[k], o);
            }
        }

        const float mk[RB] = {mv.x, mv.y, mv.z, mv.w};
        float sc[RB];
        #pragma unroll
        for (int k = 0; k < RB; k++) {
            const float mu   = s1[k] * (1.0f / DDIM);
            const float var  = s2[k] * (1.0f / DDIM) - mu * mu;
            const float rstd = rsqrtf(var + LN_EPS);
            sc[k] = rstd * sd[k] + score_c + (1.0f - mk[k]) * (-1.0e9f);
        }

        // One rescale per 4 rows.
        float mnew = m;
        #pragma unroll
        for (int k = 0; k < RB; k++) mnew = fmaxf(mnew, sc[k]);
        const float cs = __expf(m - mnew);
        float p[RB];
        float psum = 0.0f;
        #pragma unroll
        for (int k = 0; k < RB; k++) { p[k] = __expf(sc[k] - mnew); psum += p[k]; }
        l = l * cs + psum;
        m = mnew;

        #pragma unroll
        for (int j = 0; j < 4; j++) {
            float a0 = acc0[j] * cs;
            float a1 = acc1[j] * cs;
            #pragma unroll
            for (int k = 0; k < RB; k++) {
                a0 = fmaf(p[k], ((const float*)&xv0[k])[j], a0);
                a1 = fmaf(p[k], ((const float*)&xv1[k])[j], a1);
            }
            acc0[j] = a0;
            acc1[j] = a1;
        }

        // All warps done reading this slot -> safe to refill.
        __syncthreads();
        if (tid == 0 && st + DEPTH < NSTG) {
            const int ns = st + DEPTH;
            const uint32_t mbar = smem_u32(&full_bar[slot]);
            mbar_expect_tx(mbar, STAGE_BYTES);
            tma_bulk_1d(smem_u32(stage_sm + slot * (STAGE_BYTES / 4)),
                        xchunk + (size_t)ns * STAGE_ROWS * DDIM,
                        STAGE_BYTES, mbar);
        }
    }

    // Combine the 8 warps of this block in shared memory.
    __shared__ float sm_acc[WARPS][DDIM];  // 8 KB
    __shared__ float sm_m[WARPS];
    __shared__ float sm_l[WARPS];

    #pragma unroll
    for (int j = 0; j < 4; j++) sm_acc[wid][lid * 4 + j]       = acc0[j];
    #pragma unroll
    for (int j = 0; j < 4; j++) sm_acc[wid][128 + lid * 4 + j] = acc1[j];
    if (lid == 0) { sm_m[wid] = m; sm_l[wid] = l; }
    __syncthreads();

    const int d = tid;                        // 0..255
    float M = -3.0e38f;
    #pragma unroll
    for (int ww = 0; ww < WARPS; ww++) M = fmaxf(M, sm_m[ww]);
    float L = 0.0f, A = 0.0f;
    #pragma unroll
    for (int ww = 0; ww < WARPS; ww++) {
        const float e = __expf(sm_m[ww] - M);
        L += e * sm_l[ww];
        A += e * sm_acc[ww][d];
    }
    const int pidx = b * CHUNKS + chunk;
    g_pacc[(size_t)pidx * DDIM + d] = A;
    if (tid == 0) { g_pm[pidx] = M; g_pl[pidx] = L; }

    // --- Split-K style combine: last block for this batch does the reduction ---
    __threadfence();
    __shared__ int s_is_last;
    __syncthreads();
    if (tid == 0) {
        const int old = atomicAdd(&g_cnt[b], 1);
        s_is_last = (old == CHUNKS - 1);
    }
    __syncthreads();

    if (s_is_last) {
        __threadfence();  // acquire: see all other blocks' partials
        float Mg = -3.0e38f;
        #pragma unroll
        for (int i = 0; i < CHUNKS; i++) Mg = fmaxf(Mg, g_pm[b * CHUNKS + i]);
        float Lg = 0.0f, Ag = 0.0f;
        #pragma unroll
        for (int i = 0; i < CHUNKS; i++) {
            const float e = __expf(g_pm[b * CHUNKS + i] - Mg);
            Lg += e * g_pl[b * CHUNKS + i];
            Ag += e * g_pacc[((size_t)(b * CHUNKS + i)) * DDIM + d];
        }
        out[b * DDIM + d] = Ag / Lg;
        __syncthreads();
        if (tid == 0) g_cnt[b] = 0;   // reset for next graph replay
    }
}

extern "C" void kernel_launch(void* const* d_in, const int* in_sizes, int n_in,
                              void* d_out, int out_size)
{
    const float* x     = (const float*)d_in[0];
    const float* mask  = (const float*)d_in[1];
    const float* gamma = (const float*)d_in[2];
    const float* beta  = (const float*)d_in[3];
    const float* w     = (const float*)d_in[4];
    const float* bias  = (const float*)d_in[5];
    float* out = (float*)d_out;

    const int dyn_smem = DEPTH * STAGE_BYTES;    // 96 KB
    cudaFuncSetAttribute(ap_fused, cudaFuncAttributeMaxDynamicSharedMemorySize,
                         dyn_smem);

    dim3 grid(CHUNKS, BDIM);
    ap_fused<<<grid, NTHR, dyn_smem>>>(x, mask, gamma, beta, w, bias, out);
}

// round 15
// speedup vs baseline: 1.3662x; 1.3662x over previous
#include <cuda_runtime.h>
#include <cuda_bf16.h>

// AttentionPooling: B=64, S=4096, D=256, fp32.
//   LN(x) over D -> Dense(1) score -> softmax over S -> out[b,d] = sum_s x_s * w_s
// R8 structure (register double buffer @ 3 CTAs/SM, rolling L2 prefetch at
// distance 2) with the prefetch spread to EVERY iteration at 2KB (half-warp)
// instead of 4KB every other iteration -> smoother DRAM request stream.
// sgw folded into the dot weight; fused last-block combine.

#define BDIM   64
#define SDIM   4096
#define DDIM   256
#define CHUNKS 32
#define RPC    (SDIM / CHUNKS)   /* 128 rows per block */
#define WARPS  8
#define NTHR   (WARPS * 32)
#define RPW    (RPC / WARPS)     /* 16 rows per warp */
#define RB     2                 /* rows per iteration */
#define NIT    (RPW / RB)        /* 8 iterations */
#define LN_EPS 1e-3f

// Split-softmax partial scratch + completion counters (static device globals).
__device__ float g_pacc[BDIM * CHUNKS * DDIM];   // 2 MB
__device__ float g_pm[BDIM * CHUNKS];
__device__ float g_pl[BDIM * CHUNKS];
__device__ int   g_cnt[BDIM];                    // zero-init; self-resetting

__device__ __forceinline__ float warp_sum(float v) {
    #pragma unroll
    for (int o = 16; o > 0; o >>= 1) v += __shfl_xor_sync(0xffffffffu, v, o);
    return v;
}

__global__ __launch_bounds__(NTHR, 3)
void ap_fused(const float* __restrict__ x, const float* __restrict__ mask,
              const float* __restrict__ gamma, const float* __restrict__ beta,
              const float* __restrict__ w, const float* __restrict__ bias,
              float* __restrict__ out)
{
    const int b     = blockIdx.y;
    const int chunk = blockIdx.x;
    const int wid   = threadIdx.x >> 5;
    const int lid   = threadIdx.x & 31;

    // Per-lane parameter slices: d = lid*4..lid*4+3 and 128+lid*4..
    const float4 gm0 = __ldg(((const float4*)gamma) + lid);
    const float4 gm1 = __ldg(((const float4*)gamma) + 32 + lid);
    const float4 ww0 = __ldg(((const float4*)w) + lid);
    const float4 ww1 = __ldg(((const float4*)w) + 32 + lid);
    const float4 bt0 = __ldg(((const float4*)beta) + lid);
    const float4 bt1 = __ldg(((const float4*)beta) + 32 + lid);

    float gw0[4] = {gm0.x*ww0.x, gm0.y*ww0.y, gm0.z*ww0.z, gm0.w*ww0.w};
    float gw1[4] = {gm1.x*ww1.x, gm1.y*ww1.y, gm1.z*ww1.z, gm1.w*ww1.w};

    const float sgw = warp_sum(gw0[0]+gw0[1]+gw0[2]+gw0[3]
                             + gw1[0]+gw1[1]+gw1[2]+gw1[3]);
    const float bw  = warp_sum(bt0.x*ww0.x + bt0.y*ww0.y + bt0.z*ww0.z + bt0.w*ww0.w
                             + bt1.x*ww1.x + bt1.y*ww1.y + bt1.z*ww1.z + bt1.w*ww1.w);
    const float score_c = bw + __ldg(bias);

    // Fold mu*sgw into the dot weight: gw' = gamma*w - sgw/D, so
    // score = rstd * dot(x, gw') + score_c.
    #pragma unroll
    for (int j = 0; j < 4; j++) gw0[j] -= sgw * (1.0f / DDIM);
    #pragma unroll
    for (int j = 0; j < 4; j++) gw1[j] -= sgw * (1.0f / DDIM);

    const float* xb = x + (size_t)b * SDIM * DDIM;
    const float* mb = mask + (size_t)b * SDIM;

    // Online softmax state (per warp; acc distributed across lanes)
    float m = -3.0e38f, l = 0.0f;
    float acc0[4] = {0.f, 0.f, 0.f, 0.f};
    float acc1[4] = {0.f, 0.f, 0.f, 0.f};

    const int row_base = chunk * RPC + wid * RPW;

    // Double-buffered rows: [buf][row] low/high float4 halves (8 float4 total).
    float4 xv0[2][RB], xv1[2][RB];
    float2 mbuf[2];

    // Prologue: load iteration 0 (streaming: x read exactly once).
    #pragma unroll
    for (int k = 0; k < RB; k++) {
        const float4* xr = (const float4*)(xb + (size_t)(row_base + k) * DDIM);
        xv0[0][k] = __ldcs(xr + lid);
        xv1[0][k] = __ldcs(xr + 32 + lid);
    }
    mbuf[0] = __ldg((const float2*)(mb + row_base));

    #pragma unroll
    for (int it = 0; it < NIT; it++) {
        const int cur = it & 1;
        const int nxt = cur ^ 1;

        // Rolling L2 prefetch at distance 2, spread to EVERY iteration:
        // lanes 0-15 cover lid*128B = 2KB = exactly the 2 rows of iteration
        // it+2 (always within this warp's own 16-row range -> never OOB).
        if (it + 2 < NIT && lid < 16) {
            const float* pf = xb + (size_t)(row_base + (it + 2) * RB) * DDIM
                            + lid * 32;
            asm volatile("prefetch.global.L2 [%0];" :: "l"(pf));
        }

        // Prefetch next iteration's rows into registers while this one computes.
        if (it + 1 < NIT) {
            const int sN = row_base + (it + 1) * RB;
            #pragma unroll
            for (int k = 0; k < RB; k++) {
                const float4* xr = (const float4*)(xb + (size_t)(sN + k) * DDIM);
                xv0[nxt][k] = __ldcs(xr + lid);
                xv1[nxt][k] = __ldcs(xr + 32 + lid);
            }
            mbuf[nxt] = __ldg((const float2*)(mb + sN));
        }

        // Per-row partials: sum(x), sum(x^2), dot(x, gw')
        float s1[RB], s2[RB], sd[RB];
        #pragma unroll
        for (int k = 0; k < RB; k++) {
            const float4 a = xv0[cur][k], c = xv1[cur][k];
            s1[k] = a.x + a.y + a.z + a.w + c.x + c.y + c.z + c.w;
            s2[k] = a.x*a.x + a.y*a.y + a.z*a.z + a.w*a.w
                  + c.x*c.x + c.y*c.y + c.z*c.z + c.w*c.w;
            sd[k] = a.x*gw0[0] + a.y*gw0[1] + a.z*gw0[2] + a.w*gw0[3]
                  + c.x*gw1[0] + c.y*gw1[1] + c.z*gw1[2] + c.w*gw1[3];
        }
        // 6 concurrent butterfly chains, 5 rounds.
        #pragma unroll
        for (int o = 16; o > 0; o >>= 1) {
            #pragma unroll
            for (int k = 0; k < RB; k++) {
                s1[k] += __shfl_xor_sync(0xffffffffu, s1[k], o);
                s2[k] += __shfl_xor_sync(0xffffffffu, s2[k], o);
                sd[k] += __shfl_xor_sync(0xffffffffu, sd[k], o);
            }
        }

        const float mk[RB] = {mbuf[cur].x, mbuf[cur].y};

        float sc[RB];
        #pragma unroll
        for (int k = 0; k < RB; k++) {
            const float mu   = s1[k] * (1.0f / DDIM);
            const float var  = s2[k] * (1.0f / DDIM) - mu * mu;
            const float rstd = rsqrtf(var + LN_EPS);
            sc[k] = rstd * sd[k] + score_c + (1.0f - mk[k]) * (-1.0e9f);
        }

        // One rescale per RB rows.
        const float mnew = fmaxf(m, fmaxf(sc[0], sc[1]));
        const float cs = __expf(m - mnew);
        const float p0 = __expf(sc[0] - mnew);
        const float p1 = __expf(sc[1] - mnew);
        l = l * cs + p0 + p1;
        m = mnew;

        #pragma unroll
        for (int j = 0; j < 4; j++) {
            acc0[j] = fmaf(p1, ((const float*)&xv0[cur][1])[j],
                      fmaf(p0, ((const float*)&xv0[cur][0])[j], acc0[j] * cs));
            acc1[j] = fmaf(p1, ((const float*)&xv1[cur][1])[j],
                      fmaf(p0, ((const float*)&xv1[cur][0])[j], acc1[j] * cs));
        }
    }

    // Combine the 8 warps of this block in shared memory.
    __shared__ float sm_acc[WARPS][DDIM];  // 8 KB
    __shared__ float sm_m[WARPS];
    __shared__ float sm_l[WARPS];

    #pragma unroll
    for (int j = 0; j < 4; j++) sm_acc[wid][lid * 4 + j]       = acc0[j];
    #pragma unroll
    for (int j = 0; j < 4; j++) sm_acc[wid][128 + lid * 4 + j] = acc1[j];
    if (lid == 0) { sm_m[wid] = m; sm_l[wid] = l; }
    __syncthreads();

    const int d = threadIdx.x;               // 0..255
    float M = -3.0e38f;
    #pragma unroll
    for (int ww = 0; ww < WARPS; ww++) M = fmaxf(M, sm_m[ww]);
    float L = 0.0f, A = 0.0f;
    #pragma unroll
    for (int ww = 0; ww < WARPS; ww++) {
        const float e = __expf(sm_m[ww] - M);
        L += e * sm_l[ww];
        A += e * sm_acc[ww][d];
    }
    const int pidx = b * CHUNKS + chunk;
    g_pacc[(size_t)pidx * DDIM + d] = A;
    if (threadIdx.x == 0) { g_pm[pidx] = M; g_pl[pidx] = L; }

    // --- Split-K style combine: last block for this batch does the reduction ---
    __threadfence();
    __shared__ int s_is_last;
    __syncthreads();
    if (threadIdx.x == 0) {
        const int old = atomicAdd(&g_cnt[b], 1);
        s_is_last = (old == CHUNKS - 1);
    }
    __syncthreads();

    if (s_is_last) {
        __threadfence();  // acquire: see all other blocks' partials
        float Mg = -3.0e38f;
        #pragma unroll
        for (int i = 0; i < CHUNKS; i++) Mg = fmaxf(Mg, g_pm[b * CHUNKS + i]);
        float Lg = 0.0f, Ag = 0.0f;
        #pragma unroll
        for (int i = 0; i < CHUNKS; i++) {
            const float e = __expf(g_pm[b * CHUNKS + i] - Mg);
            Lg += e * g_pl[b * CHUNKS + i];
            Ag += e * g_pacc[((size_t)(b * CHUNKS + i)) * DDIM + d];
        }
        out[b * DDIM + d] = Ag / Lg;
        __syncthreads();
        if (threadIdx.x == 0) g_cnt[b] = 0;   // reset for next graph replay
    }
}

extern "C" void kernel_launch(void* const* d_in, const int* in_sizes, int n_in,
                              void* d_out, int out_size)
{
    const float* x     = (const float*)d_in[0];
    const float* mask  = (const float*)d_in[1];
    const float* gamma = (const float*)d_in[2];
    const float* beta  = (const float*)d_in[3];
    const float* w     = (const float*)d_in[4];
    const float* bias  = (const float*)d_in[5];
    float* out = (float*)d_out;

    dim3 grid(CHUNKS, BDIM);
    ap_fused<<<grid, NTHR>>>(x, mask, gamma, beta, w, bias, out);
}